// round 5
// baseline (speedup 1.0000x reference)
#include <cuda_runtime.h>
#include <cuda_bf16.h>
#include <math.h>
#include <stdint.h>

#define N_SEQS   2048
#define SEQ_LEN  512
#define N_AA     20
#define M_MI     100
#define N_PAIRS  4950                    // 100*99/2 upper triangle
#define OUT_PSSM 0
#define OUT_CONS (SEQ_LEN * N_AA)        // 10240
#define OUT_MI   (OUT_CONS + SEQ_LEN)    // 10752
#define OUT_TOTAL (OUT_MI + SEQ_LEN * SEQ_LEN)  // 272896
#define GHIST_WORDS (N_PAIRS * 200)      // 2 packed 16-bit bins per word (400 bins)

// Scratch (no dynamic allocation allowed)
__device__ unsigned char g_colpack[128 * N_SEQS];    // column-major int8 msa[:, :128] (100 used)
__device__ int           g_counts[SEQ_LEN * 21];     // per-position AA counts (incl gap)
__device__ unsigned int  g_hist[GHIST_WORDS];        // L2-resident per-pair counters (REDG target)

// ---------------------------------------------------------------------------
// Pack columns 0..99 into int8 column-major (coalesced reads, lane = column)
// AND zero the MI output region + g_counts (replaces memset nodes).
// grid (4, 32) x 256 = 32768 threads.
// ---------------------------------------------------------------------------
__global__ __launch_bounds__(256) void pack_kernel(const int* __restrict__ msa,
                                                   float* __restrict__ out) {
    int tid = threadIdx.x, lane = tid & 31, w = tid >> 5;

    // Zero MI region (512*512 floats = 65536 float4) + counts
    int gtid = (blockIdx.y * 4 + blockIdx.x) * 256 + tid;
    float4* o4 = (float4*)(out + OUT_MI);
    float4 z = make_float4(0.f, 0.f, 0.f, 0.f);
    o4[gtid] = z;
    o4[gtid + 32768] = z;
    if (gtid < SEQ_LEN * 21) g_counts[gtid] = 0;

    int col   = blockIdx.x * 32 + lane;
    int rbase = blockIdx.y * 64 + w * 8;
    bool dopack = (col < M_MI);

    uint32_t p0 = 0, p1 = 0;
#pragma unroll
    for (int s = 0; s < 4; s++) {
        p0 |= (uint32_t)msa[(rbase + s)     * SEQ_LEN + col] << (8 * s);
        p1 |= (uint32_t)msa[(rbase + 4 + s) * SEQ_LEN + col] << (8 * s);
    }
    if (dopack) {
        *(uint32_t*)&g_colpack[col * N_SEQS + rbase]     = p0;
        *(uint32_t*)&g_colpack[col * N_SEQS + rbase + 4] = p1;
    }
}

// ---------------------------------------------------------------------------
// Per-position AA counts: per-warp replica histograms -> no atomics in the
// hot loop. grid (16, 16) x 256.
// ---------------------------------------------------------------------------
__global__ __launch_bounds__(256) void count_kernel(const int* __restrict__ msa) {
    __shared__ int cnt[8][32][21];     // [warp][lane(col)][symbol]
    int tid = threadIdx.x, lane = tid & 31, w = tid >> 5;
    for (int v = tid; v < 8 * 32 * 21; v += 256) ((int*)cnt)[v] = 0;
    __syncthreads();

    int col   = blockIdx.x * 32 + lane;
    int rbase = blockIdx.y * 128 + w * 16;
    int* my = cnt[w][lane];
#pragma unroll
    for (int s = 0; s < 16; s++) {
        int c = msa[(rbase + s) * SEQ_LEN + col];   // coalesced 128B per warp
        my[c] += 1;                                  // private: plain RMW
    }
    __syncthreads();

    for (int v = tid; v < 32 * 21; v += 256) {
        int l = v / 21, c = v % 21;
        int s = 0;
#pragma unroll
        for (int ww = 0; ww < 8; ww++) s += cnt[ww][l][c];
        if (s) atomicAdd(&g_counts[(blockIdx.x * 32 + l) * 21 + c], s);
    }
}

// ---------------------------------------------------------------------------
// PSSM + conservation: one warp per position (lane = amino acid).
// ---------------------------------------------------------------------------
__global__ __launch_bounds__(256) void pssm_kernel(float* __restrict__ out, const float* __restrict__ pc) {
    int gtid = blockIdx.x * blockDim.x + threadIdx.x;
    int p = gtid >> 5, lane = gtid & 31;
    if (p >= SEQ_LEN) return;

    int ct = (lane < 20) ? g_counts[p * 21 + lane] : 0;

    int t = ct;
#pragma unroll
    for (int off = 16; off; off >>= 1) t += __shfl_xor_sync(0xffffffffu, t, off);
    int total = t;

    float pcount = 0.01f * pc[0];
    float inv_den = 1.0f / ((float)N_SEQS + pcount * 20.0f);
    float tinv = 1.0f / fmaxf((float)total, 1.0f);

    float ent = 0.0f;
    if (lane < 20) {
        float freq = ((float)ct + pcount) * inv_den;
        out[OUT_PSSM + p * 20 + lane] = logf(freq * 20.0f + 1e-10f);
        float f = (float)ct * tinv;
        ent = -f * log2f(f + 1e-10f);
    }
#pragma unroll
    for (int off = 16; off; off >>= 1) ent += __shfl_xor_sync(0xffffffffu, ent, off);
    if (lane == 0)
        out[OUT_CONS + p] = (total > 0) ? (1.0f - ent * (1.0f / 4.321928094887362f)) : 0.0f;
}

// ---------------------------------------------------------------------------
// MI: one warp per (i<j) pair (Round-3 proven shape). Gap events predicated
// out. DUAL-UNIT COUNTING: 75% of events hit the per-warp smem histogram
// (ATOMS unit); 25% (q==3) fire REDG into g_hist packed 16-bit counters
// (L2 atomic ALU — an independent hardware unit). Merged before the
// LUT-based epilogue (no MUFU in the hot path).
// ---------------------------------------------------------------------------
__global__ __launch_bounds__(256) void mi_kernel(float* __restrict__ mi_out) {
    __shared__ int   hist[8][400];
    __shared__ float lut[2049];       // log2(0..2048)
    __shared__ float slra[8][20];
    __shared__ float slcb[8][20];

    int tid = threadIdx.x, wid = tid >> 5, lane = tid & 31;
    for (int v = tid; v < 2049; v += 256) lut[v] = log2f((float)v);
    __syncthreads();

    int pid = blockIdx.x * 8 + wid;
    if (pid >= N_PAIRS) return;

    // Decode upper-triangle pair index -> (i, j), i < j; T(i) = i*(199-i)/2
    float d = sqrtf(39601.0f - 8.0f * (float)pid);
    int i = (int)((199.0f - d) * 0.5f);
    if (i < 0) i = 0;
    if (i > 98) i = 98;
    while ((((i + 1) * (199 - (i + 1))) >> 1) <= pid) ++i;
    while (((i * (199 - i)) >> 1) > pid) --i;
    int j = pid - ((i * (199 - i)) >> 1) + i + 1;

    int* h = hist[wid];
    for (int v = lane; v < 400; v += 32) h[v] = 0;
    unsigned int* gh = &g_hist[pid * 200];
    __syncwarp();

    const uint4* ca = (const uint4*)(g_colpack + i * N_SEQS);
    const uint4* cb = (const uint4*)(g_colpack + j * N_SEQS);
#pragma unroll
    for (int it = 0; it < 4; it++) {                // 4 x LDG.128 per operand
        uint4 va = ca[lane + 32 * it];
        uint4 vb = cb[lane + 32 * it];
        const uint32_t wa_[4] = {va.x, va.y, va.z, va.w};
        const uint32_t wb_[4] = {vb.x, vb.y, vb.z, vb.w};
#pragma unroll
        for (int q = 0; q < 4; q++) {
            uint32_t wa = wa_[q], wb = wb_[q];
#pragma unroll
            for (int s = 0; s < 4; s++) {
                int a = (wa >> (8 * s)) & 255;
                int b = (wb >> (8 * s)) & 255;
                if (a < 20 && b < 20) {
                    int c = a * 20 + b;
                    if (q == 3) {                   // 25% of events -> L2 atomics
                        unsigned int inc = (c & 1) ? 65536u : 1u;
                        atomicAdd(&gh[c >> 1], inc);   // no return use -> RED.E.ADD
                    } else {                         // 75% -> smem ATOMS
                        atomicAdd(&h[c], 1);
                    }
                }
            }
        }
    }
    __syncwarp();
    __threadfence();                  // order this warp's REDGs before reads
    __syncwarp();

    // Merge the L2 counters into the smem histogram (13 LDG.cg per lane)
    for (int c = lane; c < 400; c += 32) {
        unsigned int gw = __ldcg(&gh[c >> 1]);
        h[c] += (int)((gw >> (16 * (c & 1))) & 0xffffu);
    }
    __syncwarp();

    // Integer marginals over the 20x20 block
    int rs = 0, cs = 0;
    if (lane < 20) {
#pragma unroll
        for (int b = 0; b < 20; b++) { rs += h[lane * 20 + b]; cs += h[b * 20 + lane]; }
        slra[wid][lane] = lut[rs];
        slcb[wid][lane] = lut[cs];
    }
    int tv = (lane < 20) ? rs : 0;
#pragma unroll
    for (int off = 16; off; off >>= 1) tv += __shfl_xor_sync(0xffffffffu, tv, off);
    int tot = tv;
    __syncwarp();

    int tots = (tot > 0) ? tot : 1;
    float lt = lut[tots];
    float acc = 0.0f;
    for (int c = lane; c < 400; c += 32) {
        int H = h[c];
        if (H > 0) {
            int a = (c * 3277) >> 16;   // c / 20 for c < 400
            int b = c - a * 20;
            acc += (float)H * (lut[H] - slra[wid][a] - slcb[wid][b] + lt);
        }
    }
#pragma unroll
    for (int off = 16; off; off >>= 1) acc += __shfl_xor_sync(0xffffffffu, acc, off);

    if (lane == 0) {
        float mi = (tot > 0) ? acc / (float)tots : 0.0f;
        mi_out[i * SEQ_LEN + j] = mi;
        mi_out[j * SEQ_LEN + i] = mi;
    }
}

// ---------------------------------------------------------------------------
// Launch graph:
//   s2: zero g_hist (3.96MB)          ─┐ (overlaps pack)
//   0 : pack(+zero MI+counts) ── fork ─┼─ mi (waits g_hist memset)
//   s1: count ── pssm ──────────────── join
// ---------------------------------------------------------------------------
extern "C" void kernel_launch(void* const* d_in, const int* in_sizes, int n_in,
                              void* d_out, int out_size) {
    const int*   msa = (const int*)d_in[0];
    const float* pc  = (const float*)d_in[1];
    float*       out = (float*)d_out;

    static cudaStream_t s1, s2;
    static cudaEvent_t e_start, e_fork, e_join, e_hist;
    static void* hist_addr = nullptr;
    static bool init = false;
    if (!init) {
        cudaStreamCreateWithFlags(&s1, cudaStreamNonBlocking);
        cudaStreamCreateWithFlags(&s2, cudaStreamNonBlocking);
        cudaEventCreateWithFlags(&e_start, cudaEventDisableTiming);
        cudaEventCreateWithFlags(&e_fork, cudaEventDisableTiming);
        cudaEventCreateWithFlags(&e_join, cudaEventDisableTiming);
        cudaEventCreateWithFlags(&e_hist, cudaEventDisableTiming);
        cudaGetSymbolAddress(&hist_addr, g_hist);
        init = true;
    }

    cudaEventRecord(e_start, 0);

    // s2: zero the L2 counter array, overlapped with pack
    cudaStreamWaitEvent(s2, e_start, 0);
    cudaMemsetAsync(hist_addr, 0, GHIST_WORDS * sizeof(unsigned int), s2);
    cudaEventRecord(e_hist, s2);

    pack_kernel<<<dim3(4, 32), 256>>>(msa, out);    // pack + zero MI region + counts
    cudaEventRecord(e_fork, 0);

    // s1: counts + pssm/conservation, hidden under mi
    cudaStreamWaitEvent(s1, e_fork, 0);
    count_kernel<<<dim3(16, 16), 256, 0, s1>>>(msa);
    pssm_kernel<<<64, 256, 0, s1>>>(out, pc);
    cudaEventRecord(e_join, s1);

    cudaStreamWaitEvent(0, e_hist, 0);
    mi_kernel<<<(N_PAIRS + 7) / 8, 256>>>(out + OUT_MI);
    cudaStreamWaitEvent(0, e_join, 0);
}